// round 6
// baseline (speedup 1.0000x reference)
#include <cuda_runtime.h>

#define FULL_MASK 0xFFFFFFFFu
typedef unsigned long long u64;

// ---------- packed f32x2 helpers (sm_100a) ----------
__device__ __forceinline__ u64 pack2(float a, float b) {
    u64 d; asm("mov.b64 %0, {%1, %2};" : "=l"(d) : "f"(a), "f"(b)); return d;
}
__device__ __forceinline__ void unpack2(u64 v, float& a, float& b) {
    asm("mov.b64 {%0, %1}, %2;" : "=f"(a), "=f"(b) : "l"(v));
}
__device__ __forceinline__ u64 fma2(u64 a, u64 b, u64 c) {
    u64 d; asm("fma.rn.f32x2 %0, %1, %2, %3;" : "=l"(d) : "l"(a), "l"(b), "l"(c)); return d;
}
__device__ __forceinline__ u64 mul2(u64 a, u64 b) {
    u64 d; asm("mul.rn.f32x2 %0, %1, %2;" : "=l"(d) : "l"(a), "l"(b)); return d;
}
__device__ __forceinline__ u64 add2(u64 a, u64 b) {
    u64 d; asm("add.rn.f32x2 %0, %1, %2;" : "=l"(d) : "l"(a), "l"(b)); return d;
}

// ---------- shared-memory ops (explicit .shared addressing) ----------
__device__ __forceinline__ void sts128(unsigned a, u64 x, u64 y) {
    asm volatile("st.shared.v2.u64 [%0], {%1, %2};" :: "r"(a), "l"(x), "l"(y) : "memory");
}
__device__ __forceinline__ void sts64(unsigned a, u64 x) {
    asm volatile("st.shared.u64 [%0], %1;" :: "r"(a), "l"(x) : "memory");
}
__device__ __forceinline__ u64 lds64(unsigned a) {
    u64 x; asm volatile("ld.shared.u64 %0, [%1];" : "=l"(x) : "r"(a) : "memory"); return x;
}
__device__ __forceinline__ void lds128(unsigned a, u64& x, u64& y) {
    asm volatile("ld.shared.v2.u64 {%0, %1}, [%2];" : "=l"(x), "=l"(y) : "r"(a) : "memory");
}

// One warp = one (b,h,w,c) site. 512 real amps = 32 lanes x 8 f32x2 regs.
// Canonical layout A0: float index i = lane*16 + k*2 + p;
//   qubit q <-> index bit (8-q): q0..q4 = lane bits 4..0, q5..q7 = k bits 2..0,
//   q8 = pair bit p.
// Transposed layout A1 (via smem pass): swaps qubits {0,1,2} <-> {5,6,7}:
//   afterwards k' bits 2..0 = q0,q1,q2 and lane' = [q5 q6 q7 q3 q4].
// Smem region per lane padded to 20 floats (80B) -> conflict-free phases.
__global__ void __launch_bounds__(256)
quanv_main(const float* __restrict__ x, const float* __restrict__ qp,
           float* __restrict__ out) {
    __shared__ float s_vc[2][3][9], s_vs[2][3][9], s_h0[3][9];
    __shared__ __align__(16) float sbuf[8][640];   // 8 warps x 32 lanes x 20 floats

    const int tid = threadIdx.x;

    // ---- per-block prep: variational cos/sin + folded layer-0 half-angles ----
    if (tid < 27) {
        int cc = tid / 9, q = tid % 9;
        s_h0[cc][q] = 0.5f * qp[cc * 16 + q];
    } else if (tid < 81) {
        int u = tid - 27;
        int l = u / 27;
        int cc = (u % 27) / 9;
        int q = u % 9;
        float s, co;
        __sincosf(0.5f * qp[((l + 1) * 3 + cc) * 16 + q], &s, &co);
        s_vc[l][cc][q] = co;
        s_vs[l][cc][q] = s;
    }
    __syncthreads();

    const int lane = tid & 31;
    const int site = (blockIdx.x * 256 + tid) >> 5;
    const int c   = site % 3;
    const int sw  = (site / 3) & 31;
    const int shh = (site / 96) & 31;
    const int b   = site / 3072;

    const unsigned sb0 = (unsigned)__cvta_generic_to_shared(sbuf[tid >> 5]);
    const unsigned wbase = sb0 + 80u * lane;                       // A0 base
    const unsigned rb = sb0 + 80u * (lane & 3) + 8u * (lane >> 2); // A1 base

    // --- Encoding RY(pi*px) with layer-0 variational RY folded in ---
    float ec[9], es[9];
#pragma unroll
    for (int q = 0; q < 9; ++q) {
        const int di = q / 3 - 1, dj = q % 3 - 1;
        const int hi = shh + di, wj = sw + dj;
        float px = 0.0f;
        if ((unsigned)hi < 32u && (unsigned)wj < 32u)
            px = x[((b * 32 + hi) * 32 + wj) * 3 + c];
        __sincosf(fmaf(1.5707963267948966f, px, s_h0[c][q]), &es[q], &ec[q]);
    }

    // --- Product state with layer-0 CNOT ring folded in (GF(2) index map) ---
    const int c0 = (lane >> 4) & 1, c1 = (lane >> 3) & 1, c2 = (lane >> 2) & 1,
              c3 = (lane >> 1) & 1, c4 = lane & 1;
    const float Pb = ((c2 ^ c1) ? es[2] : ec[2]) * ((c3 ^ c2) ? es[3] : ec[3]) *
                     ((c4 ^ c3) ? es[4] : ec[4]);
    const float P0 = Pb * (c0 ? es[0] : ec[0]) * ((c1 ^ c0) ? es[1] : ec[1]);
    const float P1 = Pb * (c0 ? ec[0] : es[0]) * ((c1 ^ c0) ? ec[1] : es[1]);
    const float G0 = c4 ? es[5] : ec[5];
    const float G1 = c4 ? ec[5] : es[5];

    u64 st2[8];
    const u64 PP  = pack2(P0, P1);
    const u64 T8a = pack2(ec[8], es[8]);
    const u64 T8b = pack2(es[8], ec[8]);
#pragma unroll
    for (int k = 0; k < 8; ++k) {
        const int k2 = (k >> 2) & 1, k1 = (k >> 1) & 1, k0 = k & 1;
        const float m = (k2 ? G1 : G0) * ((k1 ^ k2) ? es[6] : ec[6]) *
                        ((k0 ^ k1) ? es[7] : ec[7]);
        st2[k] = mul2(mul2(PP, pack2(m, m)), k0 ? T8b : T8a);
    }

    // =============== Layer 1 (plain basis) ===============
    // reg RYs q5,q6,q7
#pragma unroll
    for (int q = 5; q < 8; ++q) {
        const int m2 = 1 << (7 - q);
        const float vc = s_vc[0][c][q], vs = s_vs[0][c][q];
        const u64 vc2 = pack2(vc, vc), vsp = pack2(vs, vs), vsn = pack2(-vs, -vs);
#pragma unroll
        for (int k = 0; k < 8; ++k)
            if (!(k & m2)) {
                const u64 a = st2[k], bb = st2[k + m2];
                st2[k]      = fma2(vc2, a,  mul2(vsn, bb));
                st2[k + m2] = fma2(vc2, bb, mul2(vsp, a));
            }
    }
    // pair RY q8
    {
        const float vc = s_vc[0][c][8], vs = s_vs[0][c][8];
        const u64 vc2 = pack2(vc, vc), vspm = pack2(-vs, vs);
#pragma unroll
        for (int k = 0; k < 8; ++k) {
            float a, bb; unpack2(st2[k], a, bb);
            st2[k] = fma2(vc2, st2[k], mul2(vspm, pack2(bb, a)));
        }
    }
    // T-in: A0 -> A1
    sts128(wbase +  0, st2[0], st2[1]);
    sts128(wbase + 16, st2[2], st2[3]);
    sts128(wbase + 32, st2[4], st2[5]);
    sts128(wbase + 48, st2[6], st2[7]);
    __syncwarp();
#pragma unroll
    for (int k = 0; k < 8; ++k) st2[k] = lds64(rb + 320u * k);
    // reg RYs q0,q1,q2 (k' bits 2,1,0)
#pragma unroll
    for (int q = 0; q < 3; ++q) {
        const int m2 = 4 >> q;
        const float vc = s_vc[0][c][q], vs = s_vs[0][c][q];
        const u64 vc2 = pack2(vc, vc), vsp = pack2(vs, vs), vsn = pack2(-vs, -vs);
#pragma unroll
        for (int k = 0; k < 8; ++k)
            if (!(k & m2)) {
                const u64 a = st2[k], bb = st2[k + m2];
                st2[k]      = fma2(vc2, a,  mul2(vsn, bb));
                st2[k + m2] = fma2(vc2, bb, mul2(vsp, a));
            }
    }
    // T-back: A1 -> A0
    __syncwarp();
#pragma unroll
    for (int k = 0; k < 8; ++k) sts64(rb + 320u * k, st2[k]);
    __syncwarp();
    lds128(wbase +  0, st2[0], st2[1]);
    lds128(wbase + 16, st2[2], st2[3]);
    lds128(wbase + 32, st2[4], st2[5]);
    lds128(wbase + 48, st2[6], st2[7]);
    // lane RYs q3 (mask 2), q4 (mask 1)
#pragma unroll
    for (int q = 3; q < 5; ++q) {
        const int m = 1 << (4 - q);
        const float vc = s_vc[0][c][q], vs = s_vs[0][c][q];
        const float svs = (lane & m) ? vs : -vs;
        const u64 vc2 = pack2(vc, vc), svs2 = pack2(svs, svs);
#pragma unroll
        for (int k = 0; k < 8; ++k) {
            float a, bb; unpack2(st2[k], a, bb);
            const float pa = __shfl_xor_sync(FULL_MASK, a, m);
            const float pb = __shfl_xor_sync(FULL_MASK, bb, m);
            st2[k] = fma2(vc2, st2[k], mul2(svs2, pack2(pa, pb)));
        }
    }

    // --- Layer-1 CNOT ring (lane segment deferred -> logical index lam) ---
    // (2) q4->5: ctrl = logical lane bit0 = parity of physical lane bits
    {
        const bool hi = (__popc(lane) & 1) != 0;
#pragma unroll
        for (int k = 0; k < 4; ++k) {
            const u64 a = st2[k], bb = st2[k + 4];
            st2[k]     = hi ? bb : a;
            st2[k + 4] = hi ? a : bb;
        }
    }
    // (3) q5->6, q6->7: vec-index renames (free)
    { u64 t = st2[4]; st2[4] = st2[6]; st2[6] = t;
          t = st2[5]; st2[5] = st2[7]; st2[7] = t; }
    { u64 t = st2[2]; st2[2] = st2[3]; st2[3] = t;
          t = st2[6]; st2[6] = st2[7]; st2[7] = t; }
    // (4) q7->8: half-swap of odd-k vecs
#pragma unroll
    for (int k = 1; k < 8; k += 2) {
        float a, bb; unpack2(st2[k], a, bb);
        st2[k] = pack2(bb, a);
    }
    // (5) q8->0: hi halves flip logical lane bit4 -> physical mask 24
#pragma unroll
    for (int k = 0; k < 8; ++k) {
        float a, bb; unpack2(st2[k], a, bb);
        bb = __shfl_xor_sync(FULL_MASK, bb, 24);
        st2[k] = pack2(a, bb);
    }

    // =============== Layer 2 ===============
    // reg RYs q5,q6,q7 + pair q8 (deferral doesn't touch reg/pair bits)
#pragma unroll
    for (int q = 5; q < 8; ++q) {
        const int m2 = 1 << (7 - q);
        const float vc = s_vc[1][c][q], vs = s_vs[1][c][q];
        const u64 vc2 = pack2(vc, vc), vsp = pack2(vs, vs), vsn = pack2(-vs, -vs);
#pragma unroll
        for (int k = 0; k < 8; ++k)
            if (!(k & m2)) {
                const u64 a = st2[k], bb = st2[k + m2];
                st2[k]      = fma2(vc2, a,  mul2(vsn, bb));
                st2[k + m2] = fma2(vc2, bb, mul2(vsp, a));
            }
    }
    {
        const float vc = s_vc[1][c][8], vs = s_vs[1][c][8];
        const u64 vc2 = pack2(vc, vc), vspm = pack2(-vs, vs);
#pragma unroll
        for (int k = 0; k < 8; ++k) {
            float a, bb; unpack2(st2[k], a, bb);
            st2[k] = fma2(vc2, st2[k], mul2(vspm, pack2(bb, a)));
        }
    }
    // T-in writing by LOGICAL lane index lam: absorbs the deferred permutation.
    {
        const int lam = lane ^ (lane >> 1) ^ (lane >> 2) ^ (lane >> 3) ^ (lane >> 4);
        const unsigned wb2 = sb0 + 80u * lam;
        __syncwarp();                       // WAR vs layer-1 T-back reads
        sts128(wb2 +  0, st2[0], st2[1]);
        sts128(wb2 + 16, st2[2], st2[3]);
        sts128(wb2 + 32, st2[4], st2[5]);
        sts128(wb2 + 48, st2[6], st2[7]);
        __syncwarp();
#pragma unroll
        for (int k = 0; k < 8; ++k) st2[k] = lds64(rb + 320u * k);
    }
    // reg RYs q0,q1,q2 (plain basis restored)
#pragma unroll
    for (int q = 0; q < 3; ++q) {
        const int m2 = 4 >> q;
        const float vc = s_vc[1][c][q], vs = s_vs[1][c][q];
        const u64 vc2 = pack2(vc, vc), vsp = pack2(vs, vs), vsn = pack2(-vs, -vs);
#pragma unroll
        for (int k = 0; k < 8; ++k)
            if (!(k & m2)) {
                const u64 a = st2[k], bb = st2[k + m2];
                st2[k]      = fma2(vc2, a,  mul2(vsn, bb));
                st2[k + m2] = fma2(vc2, bb, mul2(vsp, a));
            }
    }
    // T-back
    __syncwarp();
#pragma unroll
    for (int k = 0; k < 8; ++k) sts64(rb + 320u * k, st2[k]);
    __syncwarp();
    lds128(wbase +  0, st2[0], st2[1]);
    lds128(wbase + 16, st2[2], st2[3]);
    lds128(wbase + 32, st2[4], st2[5]);
    lds128(wbase + 48, st2[6], st2[7]);
    // lane RYs q3, q4 (plain masks 2, 1)
#pragma unroll
    for (int q = 3; q < 5; ++q) {
        const int m = 1 << (4 - q);
        const float vc = s_vc[1][c][q], vs = s_vs[1][c][q];
        const float svs = (lane & m) ? vs : -vs;
        const u64 vc2 = pack2(vc, vc), svs2 = pack2(svs, svs);
#pragma unroll
        for (int k = 0; k < 8; ++k) {
            float a, bb; unpack2(st2[k], a, bb);
            const float pa = __shfl_xor_sync(FULL_MASK, a, m);
            const float pb = __shfl_xor_sync(FULL_MASK, bb, m);
            st2[k] = fma2(vc2, st2[k], mul2(svs2, pack2(pa, pb)));
        }
    }

    // --- Measurement (plain basis; layer-2 ring conjugated into sign masks) ---
    u64 accE = 0ull, accO = 0ull;
#pragma unroll
    for (int k = 0; k < 8; ++k) {
        const u64 p = mul2(st2[k], st2[k]);
        if ((0x69 >> k) & 1) accE = add2(accE, p);
        else                 accO = add2(accO, p);
    }
    float e0, e1, o0, o1;
    unpack2(accE, e0, e1); unpack2(accO, o0, o1);
    const float sp = e0 + o1, sm = e1 + o0;
    const float tot = sp + sm;
    const float dif = sp - sm;

    // z0: full 5-level reduce
    float u = (__popc(lane & 0x0F) & 1) ? -dif : dif;
    u += __shfl_xor_sync(FULL_MASK, u, 16);
    u += __shfl_xor_sync(FULL_MASK, u, 8);
    u += __shfl_xor_sync(FULL_MASK, u, 4);
    u += __shfl_xor_sync(FULL_MASK, u, 2);
    u += __shfl_xor_sync(FULL_MASK, u, 1);

    // z1/z2 factored: reduce within bit2-class (masks 16,8,2,1), then cross (4)
    float y = (__popc(lane & 0x18) & 1) ? -tot : tot;
    y += __shfl_xor_sync(FULL_MASK, y, 16);
    y += __shfl_xor_sync(FULL_MASK, y, 8);
    y += __shfl_xor_sync(FULL_MASK, y, 2);
    y += __shfl_xor_sync(FULL_MASK, y, 1);
    const float w = __shfl_xor_sync(FULL_MASK, y, 4);

    if (lane == 0) {                 // lane 0 has bit2=0: z2 = y - w
        out[3 * site + 0] = u;
        out[3 * site + 1] = y + w;
        out[3 * site + 2] = y - w;
    }
}

extern "C" void kernel_launch(void* const* d_in, const int* in_sizes, int n_in,
                              void* d_out, int out_size) {
    const float* x  = (const float*)d_in[0];
    const float* qp = (const float*)d_in[1];
    float* out = (float*)d_out;
    quanv_main<<<3072, 256>>>(x, qp, out);
}

// round 7
// speedup vs baseline: 1.1402x; 1.1402x over previous
#include <cuda_runtime.h>

#define FULL_MASK 0xFFFFFFFFu
typedef unsigned long long u64;

// ---------- packed f32x2 helpers (sm_100a) ----------
__device__ __forceinline__ u64 pack2(float a, float b) {
    u64 d; asm("mov.b64 %0, {%1, %2};" : "=l"(d) : "f"(a), "f"(b)); return d;
}
__device__ __forceinline__ void unpack2(u64 v, float& a, float& b) {
    asm("mov.b64 {%0, %1}, %2;" : "=f"(a), "=f"(b) : "l"(v));
}
__device__ __forceinline__ u64 fma2(u64 a, u64 b, u64 c) {
    u64 d; asm("fma.rn.f32x2 %0, %1, %2, %3;" : "=l"(d) : "l"(a), "l"(b), "l"(c)); return d;
}
__device__ __forceinline__ u64 mul2(u64 a, u64 b) {
    u64 d; asm("mul.rn.f32x2 %0, %1, %2;" : "=l"(d) : "l"(a), "l"(b)); return d;
}
__device__ __forceinline__ u64 add2(u64 a, u64 b) {
    u64 d; asm("add.rn.f32x2 %0, %1, %2;" : "=l"(d) : "l"(a), "l"(b)); return d;
}

// One warp = one (b,h,w,c) site. 512 real amps = 32 lanes x 8 f32x2 regs.
// Qubit q <-> bit (8-q): qubits 0-4 lane bits, 5-7 vec-index bits, 8 in-pair.
// The layer-1 CNOT lane permutation (q0..3 ring segment) is DEFERRED: after
// that point, physical lane L holds logical index lam(L) = L^(L>>1)^...^(L>>4);
// logical xor-m butterflies become physical shfl_xor with mask pi(m)=m^(m>>1).
__global__ void __launch_bounds__(256, 6)
quanv_main(const float* __restrict__ x, const float* __restrict__ qp,
           float* __restrict__ out) {
    __shared__ float s_vc[2][3][9], s_vs[2][3][9], s_h0[3][9];

    const int tid = threadIdx.x;

    // ---- per-block prep: variational cos/sin + folded layer-0 half-angles ----
    if (tid < 27) {
        int cc = tid / 9, q = tid % 9;
        s_h0[cc][q] = 0.5f * qp[cc * 16 + q];
    } else if (tid < 81) {
        int u = tid - 27;
        int l = u / 27;
        int cc = (u % 27) / 9;
        int q = u % 9;
        float s, co;
        __sincosf(0.5f * qp[((l + 1) * 3 + cc) * 16 + q], &s, &co);
        s_vc[l][cc][q] = co;
        s_vs[l][cc][q] = s;
    }
    __syncthreads();

    const int lane = tid & 31;
    const int site = (blockIdx.x * 256 + tid) >> 5;
    const int c   = site % 3;
    const int sw  = (site / 3) & 31;
    const int shh = (site / 96) & 31;
    const int b   = site / 3072;

    // --- Encoding RY(pi*px) with layer-0 variational RY folded in ---
    float ec[9], es[9];
#pragma unroll
    for (int q = 0; q < 9; ++q) {
        const int di = q / 3 - 1, dj = q % 3 - 1;
        const int hi = shh + di, wj = sw + dj;
        float px = 0.0f;
        if ((unsigned)hi < 32u && (unsigned)wj < 32u)
            px = x[((b * 32 + hi) * 32 + wj) * 3 + c];
        __sincosf(fmaf(1.5707963267948966f, px, s_h0[c][q]), &es[q], &ec[q]);
    }

    // --- Product state with layer-0 CNOT ring folded in (GF(2) index map) ---
    const int c0 = (lane >> 4) & 1, c1 = (lane >> 3) & 1, c2 = (lane >> 2) & 1,
              c3 = (lane >> 1) & 1, c4 = lane & 1;
    const float Pb = ((c2 ^ c1) ? es[2] : ec[2]) * ((c3 ^ c2) ? es[3] : ec[3]) *
                     ((c4 ^ c3) ? es[4] : ec[4]);
    const float P0 = Pb * (c0 ? es[0] : ec[0]) * ((c1 ^ c0) ? es[1] : ec[1]); // q8=0
    const float P1 = Pb * (c0 ? ec[0] : es[0]) * ((c1 ^ c0) ? ec[1] : es[1]); // q8=1
    const float G0 = c4 ? es[5] : ec[5];
    const float G1 = c4 ? ec[5] : es[5];

    u64 st2[8];
    const u64 PP  = pack2(P0, P1);
    const u64 T8a = pack2(ec[8], es[8]);
    const u64 T8b = pack2(es[8], ec[8]);
#pragma unroll
    for (int k = 0; k < 8; ++k) {
        const int k2 = (k >> 2) & 1, k1 = (k >> 1) & 1, k0 = k & 1;
        const float m = (k2 ? G1 : G0) * ((k1 ^ k2) ? es[6] : ec[6]) *
                        ((k0 ^ k1) ? es[7] : ec[7]);
        st2[k] = mul2(mul2(PP, pack2(m, m)), k0 ? T8b : T8a);
    }

    // logical lane index once the layer-1 lane permutation is deferred
    const int lam = lane ^ (lane >> 1) ^ (lane >> 2) ^ (lane >> 3) ^ (lane >> 4);

    // ================= Layer 1 =================
    // RYs on lane-bit qubits 0..4 (pre-deferral: logical == physical)
#pragma unroll
    for (int q = 0; q < 5; ++q) {
        const int m = 1 << (4 - q);
        const float vc = s_vc[0][c][q], vs = s_vs[0][c][q];
        const float svs = (lane & m) ? vs : -vs;
        const u64 vc2 = pack2(vc, vc), svs2 = pack2(svs, svs);
#pragma unroll
        for (int k = 0; k < 8; ++k) {
            float a, bb; unpack2(st2[k], a, bb);
            const float pa = __shfl_xor_sync(FULL_MASK, a, m);
            const float pb = __shfl_xor_sync(FULL_MASK, bb, m);
            st2[k] = fma2(vc2, st2[k], mul2(svs2, pack2(pa, pb)));
        }
    }
    // RYs on vec-index qubits 5..7
#pragma unroll
    for (int q = 5; q < 8; ++q) {
        const int m2 = 1 << (7 - q);
        const float vc = s_vc[0][c][q], vs = s_vs[0][c][q];
        const u64 vc2 = pack2(vc, vc), vsp = pack2(vs, vs), vsn = pack2(-vs, -vs);
#pragma unroll
        for (int k = 0; k < 8; ++k)
            if (!(k & m2)) {
                const u64 a = st2[k], bb = st2[k + m2];
                st2[k]      = fma2(vc2, a,  mul2(vsn, bb));
                st2[k + m2] = fma2(vc2, bb, mul2(vsp, a));
            }
    }
    // RY on in-pair qubit 8
    {
        const float vc = s_vc[0][c][8], vs = s_vs[0][c][8];
        const u64 vc2 = pack2(vc, vc), vspm = pack2(-vs, vs);
#pragma unroll
        for (int k = 0; k < 8; ++k) {
            float a, bb; unpack2(st2[k], a, bb);
            st2[k] = fma2(vc2, st2[k], mul2(vspm, pack2(bb, a)));
        }
    }

    // --- Layer-1 CNOT ring ---
    // (1) q0..3 lane->lane segment: DEFERRED (index relabeling only).
    // (2) q4->5: ctrl = logical lane bit0 = parity of physical lane bits.
    {
        const bool hi = (__popc(lane) & 1) != 0;
#pragma unroll
        for (int k = 0; k < 4; ++k) {
            const u64 a = st2[k], bb = st2[k + 4];
            st2[k]     = hi ? bb : a;
            st2[k + 4] = hi ? a : bb;
        }
    }
    // (3) q5->6, q6->7: vec-index renames (free)
    { u64 t = st2[4]; st2[4] = st2[6]; st2[6] = t;
          t = st2[5]; st2[5] = st2[7]; st2[7] = t; }
    { u64 t = st2[2]; st2[2] = st2[3]; st2[3] = t;
          t = st2[6]; st2[6] = st2[7]; st2[7] = t; }
    // (4) q7->8: half-swap of odd-k vecs
#pragma unroll
    for (int k = 1; k < 8; k += 2) {
        float a, bb; unpack2(st2[k], a, bb);
        st2[k] = pack2(bb, a);
    }
    // (5) q8->0: hi halves flip logical lane bit4 -> physical mask pi(16)=24
#pragma unroll
    for (int k = 0; k < 8; ++k) {
        float a, bb; unpack2(st2[k], a, bb);
        bb = __shfl_xor_sync(FULL_MASK, bb, 24);
        st2[k] = pack2(a, bb);
    }

    // ================= Layer 2 (deferred-permutation space) =================
    // lane-bit RYs: physical shuffle mask pi(m) = m ^ (m>>1); sign from lam & m.
    {
        const int pmask[5] = {24, 12, 6, 3, 1};
#pragma unroll
        for (int q = 0; q < 5; ++q) {
            const int lm = 1 << (4 - q);
            const int pm = pmask[q];
            const float vc = s_vc[1][c][q], vs = s_vs[1][c][q];
            const float svs = (lam & lm) ? vs : -vs;
            const u64 vc2 = pack2(vc, vc), svs2 = pack2(svs, svs);
#pragma unroll
            for (int k = 0; k < 8; ++k) {
                float a, bb; unpack2(st2[k], a, bb);
                const float pa = __shfl_xor_sync(FULL_MASK, a, pm);
                const float pb = __shfl_xor_sync(FULL_MASK, bb, pm);
                st2[k] = fma2(vc2, st2[k], mul2(svs2, pack2(pa, pb)));
            }
        }
    }
#pragma unroll
    for (int q = 5; q < 8; ++q) {
        const int m2 = 1 << (7 - q);
        const float vc = s_vc[1][c][q], vs = s_vs[1][c][q];
        const u64 vc2 = pack2(vc, vc), vsp = pack2(vs, vs), vsn = pack2(-vs, -vs);
#pragma unroll
        for (int k = 0; k < 8; ++k)
            if (!(k & m2)) {
                const u64 a = st2[k], bb = st2[k + m2];
                st2[k]      = fma2(vc2, a,  mul2(vsn, bb));
                st2[k + m2] = fma2(vc2, bb, mul2(vsp, a));
            }
    }
    {
        const float vc = s_vc[1][c][8], vs = s_vs[1][c][8];
        const u64 vc2 = pack2(vc, vc), vspm = pack2(-vs, vs);
#pragma unroll
        for (int k = 0; k < 8; ++k) {
            float a, bb; unpack2(st2[k], a, bb);
            st2[k] = fma2(vc2, st2[k], mul2(vspm, pack2(bb, a)));
        }
    }

    // --- Measurement (layer-2 ring conjugated into diagonal Pauli strings) ---
    u64 accE = 0ull, accO = 0ull;
#pragma unroll
    for (int k = 0; k < 8; ++k) {
        const u64 p = mul2(st2[k], st2[k]);
        if ((0x69 >> k) & 1) accE = add2(accE, p);
        else                 accO = add2(accO, p);
    }
    float e0, e1, o0, o1;
    unpack2(accE, e0, e1); unpack2(accO, o0, o1);
    const float sp = e0 + o1, sm = e1 + o0;
    const float tot = sp + sm;
    const float dif = sp - sm;

    // z0 = sum s0(lam)*dif : full 5-level reduce
    float u = (__popc(lam & 0x0F) & 1) ? -dif : dif;
    u += __shfl_xor_sync(FULL_MASK, u, 16);
    u += __shfl_xor_sync(FULL_MASK, u, 8);
    u += __shfl_xor_sync(FULL_MASK, u, 4);
    u += __shfl_xor_sync(FULL_MASK, u, 2);
    u += __shfl_xor_sync(FULL_MASK, u, 1);

    // z1 = sum s1(lam)*tot ; z2 = sum s2(lam)*tot, s2 = s1 * (-1)^{b2(lam)}.
    // Reduce y over the 16-lane subgroup preserving b2(lam)=parity(lane&0x1C)
    // (masks 1,2,12,20), then one cross-class shuffle (mask 4).
    float y = (__popc(lam & 0x18) & 1) ? -tot : tot;
    y += __shfl_xor_sync(FULL_MASK, y, 1);
    y += __shfl_xor_sync(FULL_MASK, y, 2);
    y += __shfl_xor_sync(FULL_MASK, y, 12);
    y += __shfl_xor_sync(FULL_MASK, y, 20);
    const float w = __shfl_xor_sync(FULL_MASK, y, 4);

    if (lane == 0) {                 // lam(0)=0 -> b2 class 0: z2 = y - w
        out[3 * site + 0] = u;
        out[3 * site + 1] = y + w;
        out[3 * site + 2] = y - w;
    }
}

extern "C" void kernel_launch(void* const* d_in, const int* in_sizes, int n_in,
                              void* d_out, int out_size) {
    const float* x  = (const float*)d_in[0];
    const float* qp = (const float*)d_in[1];
    float* out = (float*)d_out;
    quanv_main<<<3072, 256>>>(x, qp, out);
}

// round 9
// speedup vs baseline: 1.2546x; 1.1003x over previous
#include <cuda_runtime.h>

#define FULL_MASK 0xFFFFFFFFu
typedef unsigned long long u64;

// ---------- packed f32x2 helpers (sm_100a) ----------
__device__ __forceinline__ u64 pack2(float a, float b) {
    u64 d; asm("mov.b64 %0, {%1, %2};" : "=l"(d) : "f"(a), "f"(b)); return d;
}
__device__ __forceinline__ void unpack2(u64 v, float& a, float& b) {
    asm("mov.b64 {%0, %1}, %2;" : "=f"(a), "=f"(b) : "l"(v));
}
__device__ __forceinline__ u64 fma2(u64 a, u64 b, u64 c) {
    u64 d; asm("fma.rn.f32x2 %0, %1, %2, %3;" : "=l"(d) : "l"(a), "l"(b), "l"(c)); return d;
}
__device__ __forceinline__ u64 mul2(u64 a, u64 b) {
    u64 d; asm("mul.rn.f32x2 %0, %1, %2;" : "=l"(d) : "l"(a), "l"(b)); return d;
}
__device__ __forceinline__ u64 add2(u64 a, u64 b) {
    u64 d; asm("add.rn.f32x2 %0, %1, %2;" : "=l"(d) : "l"(a), "l"(b)); return d;
}

// ---------- circuit building blocks (operate on one 8-vec state) ----------
__device__ __forceinline__ void laneRY(u64* st, int m, u64 vc2, u64 svs2) {
#pragma unroll
    for (int k = 0; k < 8; ++k) {
        float a, bb; unpack2(st[k], a, bb);
        const float pa = __shfl_xor_sync(FULL_MASK, a, m);
        const float pb = __shfl_xor_sync(FULL_MASK, bb, m);
        st[k] = fma2(vc2, st[k], mul2(svs2, pack2(pa, pb)));
    }
}
__device__ __forceinline__ void regRY(u64* st, int m2, u64 vc2, u64 vsp, u64 vsn) {
#pragma unroll
    for (int k = 0; k < 8; ++k)
        if (!(k & m2)) {
            const u64 a = st[k], bb = st[k + m2];
            st[k]      = fma2(vc2, a,  mul2(vsn, bb));
            st[k + m2] = fma2(vc2, bb, mul2(vsp, a));
        }
}
__device__ __forceinline__ void pairRY(u64* st, u64 vc2, u64 vspm) {
#pragma unroll
    for (int k = 0; k < 8; ++k) {
        float a, bb; unpack2(st[k], a, bb);
        st[k] = fma2(vc2, st[k], mul2(vspm, pack2(bb, a)));
    }
}
// Layer-1 CNOT ring tail (lane segment q0..3 deferred to logical relabeling)
__device__ __forceinline__ void ringTail(u64* st, bool hi) {
    // q4->5: ctrl = logical lane bit0 (parity of physical lane bits)
#pragma unroll
    for (int k = 0; k < 4; ++k) {
        const u64 a = st[k], bb = st[k + 4];
        st[k]     = hi ? bb : a;
        st[k + 4] = hi ? a : bb;
    }
    // q5->6, q6->7: vec-index renames (free)
    { u64 t = st[4]; st[4] = st[6]; st[6] = t;
          t = st[5]; st[5] = st[7]; st[7] = t; }
    { u64 t = st[2]; st[2] = st[3]; st[3] = t;
          t = st[6]; st[6] = st[7]; st[7] = t; }
    // q7->8: half-swap of odd-k vecs
#pragma unroll
    for (int k = 1; k < 8; k += 2) {
        float a, bb; unpack2(st[k], a, bb);
        st[k] = pack2(bb, a);
    }
    // q8->0: hi halves flip logical lane bit4 -> physical mask pi(16)=24
#pragma unroll
    for (int k = 0; k < 8; ++k) {
        float a, bb; unpack2(st[k], a, bb);
        bb = __shfl_xor_sync(FULL_MASK, bb, 24);
        st[k] = pack2(a, bb);
    }
}

// Encoding + product state (layer-0 RYs and CNOT ring folded in)
__device__ __forceinline__ void buildState(
    u64* st, const float* __restrict__ x, const float (*s_h0)[9],
    int b, int shh, int sw, int c, int lane
) {
    float ec[9], es[9];
#pragma unroll
    for (int q = 0; q < 9; ++q) {
        const int di = q / 3 - 1, dj = q % 3 - 1;
        const int hi = shh + di, wj = sw + dj;
        float px = 0.0f;
        if ((unsigned)hi < 32u && (unsigned)wj < 32u)
            px = x[((b * 32 + hi) * 32 + wj) * 3 + c];
        __sincosf(fmaf(1.5707963267948966f, px, s_h0[c][q]), &es[q], &ec[q]);
    }
    const int c0 = (lane >> 4) & 1, c1 = (lane >> 3) & 1, c2 = (lane >> 2) & 1,
              c3 = (lane >> 1) & 1, c4 = lane & 1;
    const float Pb = ((c2 ^ c1) ? es[2] : ec[2]) * ((c3 ^ c2) ? es[3] : ec[3]) *
                     ((c4 ^ c3) ? es[4] : ec[4]);
    const float P0 = Pb * (c0 ? es[0] : ec[0]) * ((c1 ^ c0) ? es[1] : ec[1]); // q8=0
    const float P1 = Pb * (c0 ? ec[0] : es[0]) * ((c1 ^ c0) ? ec[1] : es[1]); // q8=1
    const float G0 = c4 ? es[5] : ec[5];
    const float G1 = c4 ? ec[5] : es[5];
    const u64 PP  = pack2(P0, P1);
    const u64 T8a = pack2(ec[8], es[8]);
    const u64 T8b = pack2(es[8], ec[8]);
#pragma unroll
    for (int k = 0; k < 8; ++k) {
        const int k2 = (k >> 2) & 1, k1 = (k >> 1) & 1, k0 = k & 1;
        const float m = (k2 ? G1 : G0) * ((k1 ^ k2) ? es[6] : ec[6]) *
                        ((k0 ^ k1) ? es[7] : ec[7]);
        st[k] = mul2(mul2(PP, pack2(m, m)), k0 ? T8b : T8a);
    }
}

// Measurement: layer-2 CNOT ring conjugated into diagonal Pauli strings.
// Results valid at lane 0.
__device__ __forceinline__ void measure(
    const u64* st, int lam, float& z0, float& z1, float& z2
) {
    u64 accE = 0ull, accO = 0ull;
#pragma unroll
    for (int k = 0; k < 8; ++k) {
        const u64 p = mul2(st[k], st[k]);
        if ((0x69 >> k) & 1) accE = add2(accE, p);
        else                 accO = add2(accO, p);
    }
    float e0, e1, o0, o1;
    unpack2(accE, e0, e1); unpack2(accO, o0, o1);
    const float sp = e0 + o1, sm = e1 + o0;
    const float tot = sp + sm;
    const float dif = sp - sm;

    float u = (__popc(lam & 0x0F) & 1) ? -dif : dif;
    u += __shfl_xor_sync(FULL_MASK, u, 16);
    u += __shfl_xor_sync(FULL_MASK, u, 8);
    u += __shfl_xor_sync(FULL_MASK, u, 4);
    u += __shfl_xor_sync(FULL_MASK, u, 2);
    u += __shfl_xor_sync(FULL_MASK, u, 1);

    float y = (__popc(lam & 0x18) & 1) ? -tot : tot;
    y += __shfl_xor_sync(FULL_MASK, y, 1);
    y += __shfl_xor_sync(FULL_MASK, y, 2);
    y += __shfl_xor_sync(FULL_MASK, y, 12);
    y += __shfl_xor_sync(FULL_MASK, y, 20);
    const float w = __shfl_xor_sync(FULL_MASK, y, 4);

    z0 = u; z1 = y + w; z2 = y - w;   // lam(0)=0 -> bit2-class 0 at lane 0
}

// One warp = TWO (b,h,w,c) sites (w=2wp and w=2wp+1, same channel): two
// independent dependency chains fill SHFL-latency stalls; coefficients shared.
__global__ void __launch_bounds__(128, 9)
quanv_main(const float* __restrict__ x, const float* __restrict__ qp,
           float* __restrict__ out) {
    __shared__ float s_vc[2][3][9], s_vs[2][3][9], s_h0[3][9];

    const int tid = threadIdx.x;

    // ---- per-block prep ----
    if (tid < 27) {
        int cc = tid / 9, q = tid % 9;
        s_h0[cc][q] = 0.5f * qp[cc * 16 + q];
    } else if (tid < 81) {
        int u = tid - 27;
        int l = u / 27;
        int cc = (u % 27) / 9;
        int q = u % 9;
        float s, co;
        __sincosf(0.5f * qp[((l + 1) * 3 + cc) * 16 + q], &s, &co);
        s_vc[l][cc][q] = co;
        s_vs[l][cc][q] = s;
    }
    __syncthreads();

    const int lane = tid & 31;
    const int wid_g = (blockIdx.x * 128 + tid) >> 5;   // 0..12287
    const int c   = wid_g % 3;
    const int wp  = (wid_g / 3) & 15;
    const int shh = (wid_g / 48) & 31;
    const int b   = wid_g / 1536;
    const int swA = 2 * wp;
    const int siteA = ((b * 32 + shh) * 32 + swA) * 3 + c;   // flat (b,h,w,c)

    u64 sA[8], sB[8];
    buildState(sA, x, s_h0, b, shh, swA,     c, lane);
    buildState(sB, x, s_h0, b, shh, swA + 1, c, lane);

    const int lam = lane ^ (lane >> 1) ^ (lane >> 2) ^ (lane >> 3) ^ (lane >> 4);

    // ================= Layer 1 =================
#pragma unroll
    for (int q = 0; q < 5; ++q) {                 // lane RYs (plain masks)
        const int m = 1 << (4 - q);
        const float vc = s_vc[0][c][q], vs = s_vs[0][c][q];
        const float svs = (lane & m) ? vs : -vs;
        const u64 vc2 = pack2(vc, vc), svs2 = pack2(svs, svs);
        laneRY(sA, m, vc2, svs2);
        laneRY(sB, m, vc2, svs2);
    }
#pragma unroll
    for (int q = 5; q < 8; ++q) {                 // reg RYs
        const int m2 = 1 << (7 - q);
        const float vc = s_vc[0][c][q], vs = s_vs[0][c][q];
        const u64 vc2 = pack2(vc, vc), vsp = pack2(vs, vs), vsn = pack2(-vs, -vs);
        regRY(sA, m2, vc2, vsp, vsn);
        regRY(sB, m2, vc2, vsp, vsn);
    }
    {                                             // pair RY q8
        const float vc = s_vc[0][c][8], vs = s_vs[0][c][8];
        const u64 vc2 = pack2(vc, vc), vspm = pack2(-vs, vs);
        pairRY(sA, vc2, vspm);
        pairRY(sB, vc2, vspm);
    }
    {                                             // CNOT ring tail
        const bool hi = (__popc(lane) & 1) != 0;
        ringTail(sA, hi);
        ringTail(sB, hi);
    }

    // ================= Layer 2 (deferred-permutation space) =================
    {
        const int pmask[5] = {24, 12, 6, 3, 1};
#pragma unroll
        for (int q = 0; q < 5; ++q) {
            const int lm = 1 << (4 - q);
            const int pm = pmask[q];
            const float vc = s_vc[1][c][q], vs = s_vs[1][c][q];
            const float svs = (lam & lm) ? vs : -vs;
            const u64 vc2 = pack2(vc, vc), svs2 = pack2(svs, svs);
            laneRY(sA, pm, vc2, svs2);
            laneRY(sB, pm, vc2, svs2);
        }
    }
#pragma unroll
    for (int q = 5; q < 8; ++q) {
        const int m2 = 1 << (7 - q);
        const float vc = s_vc[1][c][q], vs = s_vs[1][c][q];
        const u64 vc2 = pack2(vc, vc), vsp = pack2(vs, vs), vsn = pack2(-vs, -vs);
        regRY(sA, m2, vc2, vsp, vsn);
        regRY(sB, m2, vc2, vsp, vsn);
    }
    {
        const float vc = s_vc[1][c][8], vs = s_vs[1][c][8];
        const u64 vc2 = pack2(vc, vc), vspm = pack2(-vs, vs);
        pairRY(sA, vc2, vspm);
        pairRY(sB, vc2, vspm);
    }

    // ================= Measurement =================
    float a0, a1, a2, b0, b1, b2;
    measure(sA, lam, a0, a1, a2);
    measure(sB, lam, b0, b1, b2);
    if (lane == 0) {
        // site B is at w+1: site index +3 (channel stride 3) -> out offset +9.
        out[3 * siteA + 0] = a0;
        out[3 * siteA + 1] = a1;
        out[3 * siteA + 2] = a2;
        out[3 * siteA + 9]  = b0;
        out[3 * siteA + 10] = b1;
        out[3 * siteA + 11] = b2;
    }
}

extern "C" void kernel_launch(void* const* d_in, const int* in_sizes, int n_in,
                              void* d_out, int out_size) {
    const float* x  = (const float*)d_in[0];
    const float* qp = (const float*)d_in[1];
    float* out = (float*)d_out;
    // 12288 warps (2 sites each) / 4 warps per 128-thread block = 3072 blocks
    quanv_main<<<3072, 128>>>(x, qp, out);
}